// round 1
// baseline (speedup 1.0000x reference)
#include <cuda_runtime.h>
#include <cstdint>
#include <math.h>

// Problem constants (FlaxGrok1SparseMoeBlock: B=2,S=1024 -> T=2048, H=1024, I=4096, E=8, K=2)
#define T_TOKENS 2048
#define HDIM 1024
#define IDIM 4096
#define NEXP 8
#define NPAIR (T_TOKENS * 2)

// ---------------- device scratch (static; no runtime allocation) ----------------
__device__ int   d_counts[NEXP];
__device__ int   d_offsets[NEXP];
__device__ int   d_cursor[NEXP];
__device__ int   d_tok[NPAIR];        // slot -> token index
__device__ float d_wt[NPAIR];         // slot -> routing weight
__device__ int   d_slot[NPAIR];       // token*2+k -> slot
__device__ int   d_te[NPAIR];         // token*2+k -> expert
__device__ float d_tw[NPAIR];         // token*2+k -> weight
__device__ float d_act[(size_t)NPAIR * IDIM];   // activations a = gelu(g)*v  (64 MB)
__device__ float d_yscr[(size_t)NPAIR * HDIM];  // per-slot weighted outputs   (16 MB)

// ---------------- kernel 0: zero expert counters ----------------
__global__ void k_zero() {
    int t = threadIdx.x;
    if (t < NEXP) d_counts[t] = 0;
}

// ---------------- kernel 1: router (logits, top-2, softmax) ----------------
__global__ void k_router(const float* __restrict__ x,
                         const float* __restrict__ Wg,
                         float* __restrict__ logits_out) {
    const int t = blockIdx.x;
    const int tid = threadIdx.x;
    const float* xr = x + (size_t)t * HDIM;

    float acc[NEXP];
#pragma unroll
    for (int e = 0; e < NEXP; e++) acc[e] = 0.f;

    for (int h = tid; h < HDIM; h += 256) {
        float xv = xr[h];
#pragma unroll
        for (int e = 0; e < NEXP; e++) acc[e] += xv * Wg[h * NEXP + e];
    }

    __shared__ float red[256];
    __shared__ float lg[NEXP];
#pragma unroll
    for (int e = 0; e < NEXP; e++) {
        red[tid] = acc[e];
        __syncthreads();
        for (int s = 128; s > 0; s >>= 1) {
            if (tid < s) red[tid] += red[tid + s];
            __syncthreads();
        }
        if (tid == 0) lg[e] = red[0];
        __syncthreads();
    }

    if (tid == 0) {
        int e0 = 0; float l0 = lg[0];
#pragma unroll
        for (int e = 1; e < NEXP; e++) if (lg[e] > l0) { l0 = lg[e]; e0 = e; }
        int e1 = -1; float l1 = -3.4e38f;
#pragma unroll
        for (int e = 0; e < NEXP; e++) if (e != e0 && lg[e] > l1) { l1 = lg[e]; e1 = e; }
        float tt = expf(l1 - l0);
        float w0 = 1.f / (1.f + tt);
        float w1 = tt / (1.f + tt);
        d_te[2 * t] = e0;     d_tw[2 * t] = w0;
        d_te[2 * t + 1] = e1; d_tw[2 * t + 1] = w1;
        atomicAdd(&d_counts[e0], 1);
        atomicAdd(&d_counts[e1], 1);
        if (logits_out) {
#pragma unroll
            for (int e = 0; e < NEXP; e++) logits_out[(size_t)t * NEXP + e] = lg[e];
        }
    }
}

// ---------------- kernel 2: exclusive scan of 8 counts ----------------
__global__ void k_scan() {
    int off = 0;
    for (int e = 0; e < NEXP; e++) {
        d_offsets[e] = off;
        d_cursor[e]  = off;
        off += d_counts[e];
    }
}

// ---------------- kernel 3: scatter token-expert pairs into expert lists ----------------
__global__ void k_scatter() {
    int i = blockIdx.x * blockDim.x + threadIdx.x;
    if (i >= NPAIR) return;
    int e = d_te[i];
    int pos = atomicAdd(&d_cursor[e], 1);
    d_tok[pos] = i >> 1;
    d_wt[pos]  = d_tw[i];
    d_slot[i]  = pos;
}

// ---------------- GELU tanh approx ----------------
__device__ __forceinline__ float gelu_tanh(float g) {
    float c = g + 0.044715f * g * g * g;
    return 0.5f * g * (1.f + tanhf(0.7978845608028654f * c));
}

// ---------------- kernel 4: fused grouped GEMM x@Win, x@Wv -> gelu(g)*v ----------------
// tile: 128 rows x 64 cols, BK=16, 256 threads, 8x4 micro-tile per thread (x2 matrices)
__global__ __launch_bounds__(256)
void k_gemm1(const float* __restrict__ x,
             const float* __restrict__ Win,
             const float* __restrict__ Wv) {
    const int e = blockIdx.z;
    const int cnt = d_counts[e];
    const int m0 = blockIdx.y * 128;
    if (m0 >= cnt) return;
    const int n0 = blockIdx.x * 64;
    const int base = d_offsets[e];
    const int tid = threadIdx.x;
    const int tr = tid >> 4;   // 0..15 (row group)
    const int tc = tid & 15;   // 0..15 (col group)

    __shared__ float As[128][17];
    __shared__ float Bg[16][64];
    __shared__ float Bv[16][64];

    // per-thread gathered row base offsets for the 8 A-load slices
    int arow[8];
#pragma unroll
    for (int l = 0; l < 8; l++) {
        int m = l * 16 + (tid >> 4);
        int gm = m0 + m;
        arow[l] = (gm < cnt) ? d_tok[base + gm] * HDIM : -1;
    }
    const int ak = tid & 15;
    const int bk = tid >> 4;
    const int bn = (tid & 15) * 4;

    float accg[8][4], accv[8][4];
#pragma unroll
    for (int i = 0; i < 8; i++)
#pragma unroll
        for (int j = 0; j < 4; j++) { accg[i][j] = 0.f; accv[i][j] = 0.f; }

    for (int k0 = 0; k0 < HDIM; k0 += 16) {
#pragma unroll
        for (int l = 0; l < 8; l++) {
            int m = l * 16 + (tid >> 4);
            As[m][ak] = (arow[l] >= 0) ? x[arow[l] + k0 + ak] : 0.f;
        }
        {
            size_t goff = ((size_t)e * HDIM + (k0 + bk)) * IDIM + n0 + bn;
            float4 vg = *(const float4*)(Win + goff);
            float4 vv = *(const float4*)(Wv + goff);
            *(float4*)&Bg[bk][bn] = vg;
            *(float4*)&Bv[bk][bn] = vv;
        }
        __syncthreads();
#pragma unroll
        for (int kk = 0; kk < 16; kk++) {
            float a[8];
#pragma unroll
            for (int i = 0; i < 8; i++) a[i] = As[tr * 8 + i][kk];
            float4 bg4 = *(const float4*)&Bg[kk][tc * 4];
            float4 bv4 = *(const float4*)&Bv[kk][tc * 4];
            float bg[4] = {bg4.x, bg4.y, bg4.z, bg4.w};
            float bv[4] = {bv4.x, bv4.y, bv4.z, bv4.w};
#pragma unroll
            for (int i = 0; i < 8; i++)
#pragma unroll
                for (int j = 0; j < 4; j++) {
                    accg[i][j] += a[i] * bg[j];
                    accv[i][j] += a[i] * bv[j];
                }
        }
        __syncthreads();
    }

#pragma unroll
    for (int i = 0; i < 8; i++) {
        int gm = m0 + tr * 8 + i;
        if (gm >= cnt) continue;
        size_t rowoff = (size_t)(base + gm) * IDIM + n0 + tc * 4;
#pragma unroll
        for (int j = 0; j < 4; j++) {
            d_act[rowoff + j] = gelu_tanh(accg[i][j]) * accv[i][j];
        }
    }
}

// ---------------- kernel 5: grouped GEMM a@Wout, scaled by routing weight ----------------
__global__ __launch_bounds__(256)
void k_gemm2(const float* __restrict__ Wout) {
    const int e = blockIdx.z;
    const int cnt = d_counts[e];
    const int m0 = blockIdx.y * 128;
    if (m0 >= cnt) return;
    const int n0 = blockIdx.x * 64;
    const int base = d_offsets[e];
    const int tid = threadIdx.x;
    const int tr = tid >> 4;
    const int tc = tid & 15;

    __shared__ float As[128][17];
    __shared__ float Bs[16][64];

    const int ak = tid & 15;
    const int bk = tid >> 4;
    const int bn = (tid & 15) * 4;

    // A rows are contiguous in d_act
    long arow[8];
#pragma unroll
    for (int l = 0; l < 8; l++) {
        int m = l * 16 + (tid >> 4);
        int gm = m0 + m;
        arow[l] = (gm < cnt) ? (long)((size_t)(base + gm) * IDIM) : -1;
    }

    float acc[8][4];
#pragma unroll
    for (int i = 0; i < 8; i++)
#pragma unroll
        for (int j = 0; j < 4; j++) acc[i][j] = 0.f;

    for (int k0 = 0; k0 < IDIM; k0 += 16) {
#pragma unroll
        for (int l = 0; l < 8; l++) {
            int m = l * 16 + (tid >> 4);
            As[m][ak] = (arow[l] >= 0) ? d_act[arow[l] + k0 + ak] : 0.f;
        }
        {
            size_t goff = ((size_t)e * IDIM + (k0 + bk)) * HDIM + n0 + bn;
            *(float4*)&Bs[bk][bn] = *(const float4*)(Wout + goff);
        }
        __syncthreads();
#pragma unroll
        for (int kk = 0; kk < 16; kk++) {
            float a[8];
#pragma unroll
            for (int i = 0; i < 8; i++) a[i] = As[tr * 8 + i][kk];
            float4 b4 = *(const float4*)&Bs[kk][tc * 4];
            float b[4] = {b4.x, b4.y, b4.z, b4.w};
#pragma unroll
            for (int i = 0; i < 8; i++)
#pragma unroll
                for (int j = 0; j < 4; j++) acc[i][j] += a[i] * b[j];
        }
        __syncthreads();
    }

#pragma unroll
    for (int i = 0; i < 8; i++) {
        int gm = m0 + tr * 8 + i;
        if (gm >= cnt) continue;
        float wt = d_wt[base + gm];
        size_t rowoff = (size_t)(base + gm) * HDIM + n0 + tc * 4;
#pragma unroll
        for (int j = 0; j < 4; j++) {
            d_yscr[rowoff + j] = acc[i][j] * wt;
        }
    }
}

// ---------------- kernel 6: combine the two expert outputs per token ----------------
__global__ void k_combine(float* __restrict__ out) {
    const int t = blockIdx.x;
    const int s0 = d_slot[2 * t];
    const int s1 = d_slot[2 * t + 1];
    const float* y0 = d_yscr + (size_t)s0 * HDIM;
    const float* y1 = d_yscr + (size_t)s1 * HDIM;
    float* o = out + (size_t)t * HDIM;
    for (int h = threadIdx.x; h < HDIM; h += 256) {
        o[h] = y0[h] + y1[h];
    }
}

// ---------------- launch ----------------
extern "C" void kernel_launch(void* const* d_in, const int* in_sizes, int n_in,
                              void* d_out, int out_size) {
    const float* x    = (const float*)d_in[0];
    const float* Wg   = (const float*)d_in[1];
    const float* Win  = (const float*)d_in[2];
    const float* Wv   = (const float*)d_in[3];
    const float* Wout = (const float*)d_in[4];
    float* out = (float*)d_out;

    float* logits = nullptr;
    if (out_size >= (int)((size_t)T_TOKENS * HDIM + (size_t)T_TOKENS * NEXP))
        logits = out + (size_t)T_TOKENS * HDIM;

    k_zero<<<1, 32>>>();
    k_router<<<T_TOKENS, 256>>>(x, Wg, logits);
    k_scan<<<1, 1>>>();
    k_scatter<<<NPAIR / 256, 256>>>();

    dim3 g1(IDIM / 64, (T_TOKENS + 127) / 128, NEXP);
    k_gemm1<<<g1, 256>>>(x, Win, Wv);

    dim3 g2(HDIM / 64, (T_TOKENS + 127) / 128, NEXP);
    k_gemm2<<<g2, 256>>>(Wout);

    k_combine<<<T_TOKENS, 256>>>(out);
}